// round 14
// baseline (speedup 1.0000x reference)
#include <cuda_runtime.h>
#include <cuda_bf16.h>
#include <cstdint>

// ---------------------------------------------------------------------------
// KAME pipeline (8 launches):
//   0) prep (ONE launch): splitB_t(dag_emb) + splitW x3 (Wih0/Wih1/fc_w)
//   1) P = inputs_x @ dag_emb partials: gemm1_mma split-K x3
//   2) xW0 = tanh(P0+P1+P2) @ Wih0^T + bih0   (gemm2_fused)
//   3) H   = GRU-scan(xW0, Whh0, bhh0)        (weights-in-regs, x-preadd)
//   4) xW1 = H @ Wih1^T + bih1                (gemmS_mma<1>)
//   5) H   = GRU-scan(xW1, Whh1, bhh1)
//   6) S   = [H, attention]  (2 bt / 256-thr CTA, NAMED barriers per half)
//   7) out = sigmoid(S @ fc_w^T + fc_b) * mask     (gemmS_mma<2>)
// ---------------------------------------------------------------------------

#define BT_TOTAL 6400
#define T_STEPS  50
#define K1       4880
#define N1       128

__device__ float g_P [3 * BT_TOTAL * 128];   // split-K partials
__device__ float g_xW[BT_TOTAL * 384];
__device__ float g_H [BT_TOTAL * 128];
__device__ float g_S [BT_TOTAL * 256];
__device__ __nv_bfloat16 g_Bth[N1 * K1];
__device__ __nv_bfloat16 g_Btl[N1 * K1];
__device__ __nv_bfloat16 g_W0h[384 * 128], g_W0l[384 * 128];
__device__ __nv_bfloat16 g_W1h[384 * 128], g_W1l[384 * 128];
__device__ __nv_bfloat16 g_Wfh[384 * 256], g_Wfl[384 * 256];

// ======================= PTX helpers =======================================
__device__ __forceinline__ uint32_t smem_u32(const void* p) {
    uint32_t a;
    asm("{ .reg .u64 t; cvta.to.shared.u64 t, %1; cvt.u32.u64 %0, t; }" : "=r"(a) : "l"(p));
    return a;
}
#define LDSM4(r, addr) \
    asm volatile("ldmatrix.sync.aligned.m8n8.x4.shared.b16 {%0,%1,%2,%3}, [%4];" \
        : "=r"((r)[0]), "=r"((r)[1]), "=r"((r)[2]), "=r"((r)[3]) : "r"(addr))
#define MMA_BF16(d, a, b) \
    asm volatile("mma.sync.aligned.m16n8k16.row.col.f32.bf16.bf16.f32 " \
        "{%0,%1,%2,%3}, {%4,%5,%6,%7}, {%8,%9}, {%0,%1,%2,%3};" \
        : "+f"((d)[0]), "+f"((d)[1]), "+f"((d)[2]), "+f"((d)[3]) \
        : "r"((a)[0]), "r"((a)[1]), "r"((a)[2]), "r"((a)[3]), \
          "r"((b)[0]), "r"((b)[1]))
#define BAR_SYNC(id, cnt) \
    asm volatile("bar.sync %0, %1;" :: "r"(id), "r"(cnt) : "memory")

__device__ __forceinline__ unsigned long long pk2(float x, float y) {
    unsigned long long r;
    asm("mov.b64 %0, {%1, %2};" : "=l"(r) : "f"(x), "f"(y));
    return r;
}
__device__ __forceinline__ void fma2(unsigned long long& d,
                                     unsigned long long a, unsigned long long b) {
    asm("fma.rn.f32x2 %0, %1, %2, %0;" : "+l"(d) : "l"(a), "l"(b));
}
__device__ __forceinline__ unsigned long long add2(unsigned long long a,
                                                   unsigned long long b) {
    unsigned long long r;
    asm("add.rn.f32x2 %0, %1, %2;" : "=l"(r) : "l"(a), "l"(b));
    return r;
}
__device__ __forceinline__ float2 upk2(unsigned long long v) {
    float lo, hi;
    asm("mov.b64 {%0, %1}, %2;" : "=f"(lo), "=f"(hi) : "l"(v));
    return make_float2(lo, hi);
}

// ---- fast transcendental helpers (MUFU-based, rel err ~1e-6) --------------
__device__ __forceinline__ float fsig(float x) {
    return __fdividef(1.f, 1.f + __expf(-x));
}
__device__ __forceinline__ float ftanh(float x) {
    return 1.f - __fdividef(2.f, 1.f + __expf(2.f * x));
}

// ======================= stage 0: fused prep (1 launch) ====================
__global__ void __launch_bounds__(256) prep_all(
    const float* __restrict__ dag,
    const float* __restrict__ W0, const float* __restrict__ W1,
    const float* __restrict__ Wf,
    __nv_bfloat16* __restrict__ Bh,  __nv_bfloat16* __restrict__ Bl,
    __nv_bfloat16* __restrict__ W0h, __nv_bfloat16* __restrict__ W0l,
    __nv_bfloat16* __restrict__ W1h, __nv_bfloat16* __restrict__ W1l,
    __nv_bfloat16* __restrict__ Wfh, __nv_bfloat16* __restrict__ Wfl)
{
    __shared__ float t[32][33];
    const int b = blockIdx.x;
    if (b < 612) {
        const int k0 = (b % 153) << 5;
        const int n0 = (b / 153) << 5;
        const int tx = threadIdx.x & 31, ty = threadIdx.x >> 5;
#pragma unroll
        for (int r = ty; r < 32; r += 8) {
            const int k = k0 + r;
            t[r][tx] = (k < K1) ? dag[(size_t)k * N1 + n0 + tx] : 0.f;
        }
        __syncthreads();
#pragma unroll
        for (int r = ty; r < 32; r += 8) {
            const int n = n0 + r, k = k0 + tx;
            if (k < K1) {
                const float v = t[tx][r];
                const __nv_bfloat16 h = __float2bfloat16(v);
                Bh[(size_t)n * K1 + k] = h;
                Bl[(size_t)n * K1 + k] = __float2bfloat16(v - __bfloat162float(h));
            }
        }
    } else {
        const float* W; __nv_bfloat16 *Wh, *Wl; int base, total, valid;
        if (b < 804)      { W = W0; Wh = W0h; Wl = W0l; base = 612; total = 49152;  valid = 49152; }
        else if (b < 996) { W = W1; Wh = W1h; Wl = W1l; base = 804; total = 49152;  valid = 49152; }
        else              { W = Wf; Wh = Wfh; Wl = Wfl; base = 996; total = 98304;  valid = 72448; }
        const int idx = (b - base) * 256 + threadIdx.x;
        if (idx < total) {
            const float v = (idx < valid) ? W[idx] : 0.f;
            const __nv_bfloat16 h = __float2bfloat16(v);
            Wh[idx] = h;
            Wl[idx] = __float2bfloat16(v - __bfloat162float(h));
        }
    }
}

// ======================= stage 1: mma.sync split GEMM (split-K x3) =========
#define S1_NCH 77
#define S1_KSPLIT 26
#define S1_SMEM (55296 * 2)

__global__ void __launch_bounds__(256) gemm1_mma(
    const float* __restrict__ A,
    const __nv_bfloat16* __restrict__ Bth,
    const __nv_bfloat16* __restrict__ Btl,
    float* __restrict__ P)
{
    extern __shared__ __align__(16) __nv_bfloat16 sm[];
    const uint32_t smb = smem_u32(sm);

    const int tid    = threadIdx.x;
    const int lane   = tid & 31;
    const int wid    = tid >> 5;
    const int warp_m = wid & 1;
    const int warp_n = wid >> 1;
    const int m0     = blockIdx.x << 6;
    const int zz     = blockIdx.y;
    const int c0     = zz * S1_KSPLIT;
    const int c1     = (c0 + S1_KSPLIT < S1_NCH) ? c0 + S1_KSPLIT : S1_NCH;
    float* const Cp  = P + (size_t)zz * BT_TOTAL * 128;

    const int a_re = (warp_m * 32 + (lane & 15)) * 72 + ((lane >> 4) << 3);
    const int b_re = (warp_n * 32 + (lane & 7) + ((lane >> 4) & 1) * 8) * 72
                   + (((lane >> 3) & 1) << 3);

    float acc[2][4][4];
#pragma unroll
    for (int i = 0; i < 2; ++i)
#pragma unroll
        for (int j = 0; j < 4; ++j)
#pragma unroll
            for (int q = 0; q < 4; ++q) acc[i][j][q] = 0.f;

    float4 ra[4];
    uint4  rbh[4], rbl[4];

    auto load_gmem = [&](int c) {
        const int k0 = c << 6;
        if (c < 76) {
#pragma unroll
            for (int p = 0; p < 4; ++p) {
                const int j = tid + (p << 8);
                const int row = j >> 4, c4 = j & 15;
                ra[p] = *(const float4*)(A + (size_t)(m0 + row) * K1 + k0 + (c4 << 2));
            }
#pragma unroll
            for (int p = 0; p < 4; ++p) {
                const int j = tid + (p << 8);
                const int row = j >> 3, ch = j & 7;
                rbh[p] = *(const uint4*)(Bth + (size_t)row * K1 + k0 + (ch << 3));
                rbl[p] = *(const uint4*)(Btl + (size_t)row * K1 + k0 + (ch << 3));
            }
        } else {
            {
                const int row = tid >> 2, c4 = tid & 3;
                ra[0] = *(const float4*)(A + (size_t)(m0 + row) * K1 + k0 + (c4 << 2));
            }
            {
                const int row = tid >> 1, ch = tid & 1;
                rbh[0] = *(const uint4*)(Bth + (size_t)row * K1 + k0 + (ch << 3));
                rbl[0] = *(const uint4*)(Btl + (size_t)row * K1 + k0 + (ch << 3));
            }
        }
    };
    auto store_smem = [&](int c, int buf) {
        const int offAh = (buf * 2 + 0) * 4608;
        const int offAl = (buf * 2 + 1) * 4608;
        const int offBh = 18432 + (buf * 2 + 0) * 9216;
        const int offBl = 18432 + (buf * 2 + 1) * 9216;
        if (c < 76) {
#pragma unroll
            for (int p = 0; p < 4; ++p) {
                const int j = tid + (p << 8);
                const int row = j >> 4, c4 = j & 15;
                const float4 v = ra[p];
                __nv_bfloat162 h01 = __float22bfloat162_rn(make_float2(v.x, v.y));
                __nv_bfloat162 h23 = __float22bfloat162_rn(make_float2(v.z, v.w));
                float2 f01 = __bfloat1622float2(h01);
                float2 f23 = __bfloat1622float2(h23);
                __nv_bfloat162 l01 = __float22bfloat162_rn(make_float2(v.x - f01.x, v.y - f01.y));
                __nv_bfloat162 l23 = __float22bfloat162_rn(make_float2(v.z - f23.x, v.w - f23.y));
                const int e = row * 72 + (c4 << 2);
                uint2 hh, ll;
                hh.x = *(uint32_t*)&h01; hh.y = *(uint32_t*)&h23;
                ll.x = *(uint32_t*)&l01; ll.y = *(uint32_t*)&l23;
                *(uint2*)(sm + offAh + e) = hh;
                *(uint2*)(sm + offAl + e) = ll;
            }
#pragma unroll
            for (int p = 0; p < 4; ++p) {
                const int j = tid + (p << 8);
                const int row = j >> 3, ch = j & 7;
                const int e = row * 72 + (ch << 3);
                *(uint4*)(sm + offBh + e) = rbh[p];
                *(uint4*)(sm + offBl + e) = rbl[p];
            }
        } else {
            {
                const int row = tid >> 2, c4 = tid & 3;
                const float4 v = ra[0];
                __nv_bfloat162 h01 = __float22bfloat162_rn(make_float2(v.x, v.y));
                __nv_bfloat162 h23 = __float22bfloat162_rn(make_float2(v.z, v.w));
                float2 f01 = __bfloat1622float2(h01);
                float2 f23 = __bfloat1622float2(h23);
                __nv_bfloat162 l01 = __float22bfloat162_rn(make_float2(v.x - f01.x, v.y - f01.y));
                __nv_bfloat162 l23 = __float22bfloat162_rn(make_float2(v.z - f23.x, v.w - f23.y));
                const int e = row * 72 + (c4 << 2);
                uint2 hh, ll;
                hh.x = *(uint32_t*)&h01; hh.y = *(uint32_t*)&h23;
                ll.x = *(uint32_t*)&l01; ll.y = *(uint32_t*)&l23;
                *(uint2*)(sm + offAh + e) = hh;
                *(uint2*)(sm + offAl + e) = ll;
            }
            {
                const int row = tid >> 1, ch = tid & 1;
                const int e = row * 72 + (ch << 3);
                *(uint4*)(sm + offBh + e) = rbh[0];
                *(uint4*)(sm + offBl + e) = rbl[0];
            }
        }
    };

    load_gmem(c0);
    store_smem(c0, 0);
    __syncthreads();

    for (int c = c0; c < c1; ++c) {
        const int buf = (c - c0) & 1;
        if (c + 1 < c1) load_gmem(c + 1);

        const uint32_t aAh = smb + ((buf * 2 + 0) * 4608 + a_re) * 2;
        const uint32_t aAl = smb + ((buf * 2 + 1) * 4608 + a_re) * 2;
        const uint32_t aBh = smb + (18432 + (buf * 2 + 0) * 9216 + b_re) * 2;
        const uint32_t aBl = smb + (18432 + (buf * 2 + 1) * 9216 + b_re) * 2;

        const int ksteps = (c < 76) ? 4 : 1;
        for (int ks = 0; ks < ksteps; ++ks) {
            const uint32_t kb = (uint32_t)(ks << 5);
            uint32_t ah[2][4], al[2][4], bh[2][4], bl[2][4];
#pragma unroll
            for (int mi = 0; mi < 2; ++mi) {
                LDSM4(ah[mi], aAh + kb + mi * (16 * 72 * 2));
                LDSM4(al[mi], aAl + kb + mi * (16 * 72 * 2));
            }
#pragma unroll
            for (int g = 0; g < 2; ++g) {
                LDSM4(bh[g], aBh + kb + g * (16 * 72 * 2));
                LDSM4(bl[g], aBl + kb + g * (16 * 72 * 2));
            }
#pragma unroll
            for (int mi = 0; mi < 2; ++mi)
#pragma unroll
                for (int nj = 0; nj < 4; ++nj) {
                    const uint32_t* ph = &bh[nj >> 1][(nj & 1) << 1];
                    const uint32_t* pl = &bl[nj >> 1][(nj & 1) << 1];
                    MMA_BF16(acc[mi][nj], ah[mi], ph);
                    MMA_BF16(acc[mi][nj], ah[mi], pl);
                    MMA_BF16(acc[mi][nj], al[mi], ph);
                }
        }
        if (c + 1 < c1) {
            store_smem(c + 1, buf ^ 1);
            __syncthreads();
        }
    }

#pragma unroll
    for (int mi = 0; mi < 2; ++mi) {
        const int row0 = m0 + warp_m * 32 + mi * 16 + (lane >> 2);
#pragma unroll
        for (int nj = 0; nj < 4; ++nj) {
            const int col = warp_n * 32 + nj * 8 + ((lane & 3) << 1);
            *(float2*)(Cp + (size_t)row0 * 128 + col) =
                make_float2(acc[mi][nj][0], acc[mi][nj][1]);
            *(float2*)(Cp + (size_t)(row0 + 8) * 128 + col) =
                make_float2(acc[mi][nj][2], acc[mi][nj][3]);
        }
    }
}

// ======================= stage 2: fused combine+tanh GEMM ==================
__global__ void __launch_bounds__(256) gemm2_fused(
    const float* __restrict__ P,
    const __nv_bfloat16* __restrict__ Bh,
    const __nv_bfloat16* __restrict__ Bl,
    const float* __restrict__ bias,
    float* __restrict__ C)
{
    extern __shared__ __align__(16) __nv_bfloat16 sm[];
    const uint32_t smb = smem_u32(sm);

    const float* P1 = P + (size_t)BT_TOTAL * 128;
    const float* P2 = P + (size_t)2 * BT_TOTAL * 128;

    const int tid    = threadIdx.x;
    const int lane   = tid & 31;
    const int wid    = tid >> 5;
    const int warp_m = wid & 1;
    const int warp_n = wid >> 1;
    const int m0     = blockIdx.x << 6;
    const int n0     = blockIdx.y << 7;

    const int a_re = (warp_m * 32 + (lane & 15)) * 72 + ((lane >> 4) << 3);
    const int b_re = (warp_n * 32 + (lane & 7) + ((lane >> 4) & 1) * 8) * 72
                   + (((lane >> 3) & 1) << 3);

    float acc[2][4][4];
#pragma unroll
    for (int i = 0; i < 2; ++i)
#pragma unroll
        for (int j = 0; j < 4; ++j)
#pragma unroll
            for (int q = 0; q < 4; ++q) acc[i][j][q] = 0.f;

    float4 ra[4];
    uint4  rbh[4], rbl[4];

    auto load_gmem = [&](int c) {
        const int k0 = c << 6;
#pragma unroll
        for (int p = 0; p < 4; ++p) {
            const int j = tid + (p << 8);
            const int row = j >> 4, c4 = j & 15;
            const size_t off = (size_t)(m0 + row) * 128 + k0 + (c4 << 2);
            const float4 a  = *(const float4*)(P  + off);
            const float4 b  = *(const float4*)(P1 + off);
            const float4 c2 = *(const float4*)(P2 + off);
            ra[p] = make_float4(a.x + b.x + c2.x, a.y + b.y + c2.y,
                                a.z + b.z + c2.z, a.w + b.w + c2.w);
        }
#pragma unroll
        for (int p = 0; p < 4; ++p) {
            const int j = tid + (p << 8);
            const int row = j >> 3, ch = j & 7;
            rbh[p] = *(const uint4*)(Bh + (size_t)(n0 + row) * 128 + k0 + (ch << 3));
            rbl[p] = *(const uint4*)(Bl + (size_t)(n0 + row) * 128 + k0 + (ch << 3));
        }
    };
    auto store_smem = [&](int buf) {
        const int offAh = (buf * 2 + 0) * 4608;
        const int offAl = (buf * 2 + 1) * 4608;
        const int offBh = 18432 + (buf * 2 + 0) * 9216;
        const int offBl = 18432 + (buf * 2 + 1) * 9216;
#pragma unroll
        for (int p = 0; p < 4; ++p) {
            const int j = tid + (p << 8);
            const int row = j >> 4, c4 = j & 15;
            float4 v = ra[p];
            v.x = ftanh(v.x); v.y = ftanh(v.y);
            v.z = ftanh(v.z); v.w = ftanh(v.w);
            __nv_bfloat162 h01 = __float22bfloat162_rn(make_float2(v.x, v.y));
            __nv_bfloat162 h23 = __float22bfloat162_rn(make_float2(v.z, v.w));
            float2 f01 = __bfloat1622float2(h01);
            float2 f23 = __bfloat1622float2(h23);
            __nv_bfloat162 l01 = __float22bfloat162_rn(make_float2(v.x - f01.x, v.y - f01.y));
            __nv_bfloat162 l23 = __float22bfloat162_rn(make_float2(v.z - f23.x, v.w - f23.y));
            const int e = row * 72 + (c4 << 2);
            uint2 hh, ll;
            hh.x = *(uint32_t*)&h01; hh.y = *(uint32_t*)&h23;
            ll.x = *(uint32_t*)&l01; ll.y = *(uint32_t*)&l23;
            *(uint2*)(sm + offAh + e) = hh;
            *(uint2*)(sm + offAl + e) = ll;
        }
#pragma unroll
        for (int p = 0; p < 4; ++p) {
            const int j = tid + (p << 8);
            const int row = j >> 3, ch = j & 7;
            const int e = row * 72 + (ch << 3);
            *(uint4*)(sm + offBh + e) = rbh[p];
            *(uint4*)(sm + offBl + e) = rbl[p];
        }
    };

    load_gmem(0);
    store_smem(0);
    __syncthreads();

#pragma unroll
    for (int c = 0; c < 2; ++c) {
        const int buf = c & 1;
        if (c == 0) load_gmem(1);

        const uint32_t aAh = smb + ((buf * 2 + 0) * 4608 + a_re) * 2;
        const uint32_t aAl = smb + ((buf * 2 + 1) * 4608 + a_re) * 2;
        const uint32_t aBh = smb + (18432 + (buf * 2 + 0) * 9216 + b_re) * 2;
        const uint32_t aBl = smb + (18432 + (buf * 2 + 1) * 9216 + b_re) * 2;

#pragma unroll
        for (int ks = 0; ks < 4; ++ks) {
            const uint32_t kb = (uint32_t)(ks << 5);
            uint32_t ah[2][4], al[2][4], bh[2][4], bl[2][4];
#pragma unroll
            for (int mi = 0; mi < 2; ++mi) {
                LDSM4(ah[mi], aAh + kb + mi * (16 * 72 * 2));
                LDSM4(al[mi], aAl + kb + mi * (16 * 72 * 2));
            }
#pragma unroll
            for (int g = 0; g < 2; ++g) {
                LDSM4(bh[g], aBh + kb + g * (16 * 72 * 2));
                LDSM4(bl[g], aBl + kb + g * (16 * 72 * 2));
            }
#pragma unroll
            for (int mi = 0; mi < 2; ++mi)
#pragma unroll
                for (int nj = 0; nj < 4; ++nj) {
                    const uint32_t* ph = &bh[nj >> 1][(nj & 1) << 1];
                    const uint32_t* pl = &bl[nj >> 1][(nj & 1) << 1];
                    MMA_BF16(acc[mi][nj], ah[mi], ph);
                    MMA_BF16(acc[mi][nj], ah[mi], pl);
                    MMA_BF16(acc[mi][nj], al[mi], ph);
                }
        }
        if (c == 0) {
            store_smem(1);
            __syncthreads();
        }
    }

#pragma unroll
    for (int mi = 0; mi < 2; ++mi) {
        const int row0 = m0 + warp_m * 32 + mi * 16 + (lane >> 2);
#pragma unroll
        for (int nj = 0; nj < 4; ++nj) {
            const int col = n0 + warp_n * 32 + nj * 8 + ((lane & 3) << 1);
            const float b0 = bias[col], b1 = bias[col + 1];
            *(float2*)(C + (size_t)row0 * 384 + col) =
                make_float2(acc[mi][nj][0] + b0, acc[mi][nj][1] + b1);
            *(float2*)(C + (size_t)(row0 + 8) * 384 + col) =
                make_float2(acc[mi][nj][2] + b0, acc[mi][nj][3] + b1);
        }
    }
}

// ======================= small mma GEMM (stages 4,7) =======================
template<int EPI>  // 1 = +bias; 2 = mask*sigmoid(+bias)
__global__ void __launch_bounds__(256) gemmS_mma(
    const float* __restrict__ A,
    const __nv_bfloat16* __restrict__ Bh,
    const __nv_bfloat16* __restrict__ Bl,
    const float* __restrict__ bias,
    const float* __restrict__ mask,
    float* __restrict__ C, int Kdim, int Nreal)
{
    extern __shared__ __align__(16) __nv_bfloat16 sm[];
    const uint32_t smb = smem_u32(sm);

    const int tid    = threadIdx.x;
    const int lane   = tid & 31;
    const int wid    = tid >> 5;
    const int warp_m = wid & 1;
    const int warp_n = wid >> 1;
    const int m0     = blockIdx.x << 6;
    const int n0     = blockIdx.y << 7;
    const int nch    = Kdim >> 6;

    const int a_re = (warp_m * 32 + (lane & 15)) * 72 + ((lane >> 4) << 3);
    const int b_re = (warp_n * 32 + (lane & 7) + ((lane >> 4) & 1) * 8) * 72
                   + (((lane >> 3) & 1) << 3);

    float acc[2][4][4];
#pragma unroll
    for (int i = 0; i < 2; ++i)
#pragma unroll
        for (int j = 0; j < 4; ++j)
#pragma unroll
            for (int q = 0; q < 4; ++q) acc[i][j][q] = 0.f;

    float4 ra[4];
    uint4  rbh[4], rbl[4];

    auto load_gmem = [&](int c) {
        const int k0 = c << 6;
#pragma unroll
        for (int p = 0; p < 4; ++p) {
            const int j = tid + (p << 8);
            const int row = j >> 4, c4 = j & 15;
            ra[p] = *(const float4*)(A + (size_t)(m0 + row) * Kdim + k0 + (c4 << 2));
        }
#pragma unroll
        for (int p = 0; p < 4; ++p) {
            const int j = tid + (p << 8);
            const int row = j >> 3, ch = j & 7;
            rbh[p] = *(const uint4*)(Bh + (size_t)(n0 + row) * Kdim + k0 + (ch << 3));
            rbl[p] = *(const uint4*)(Bl + (size_t)(n0 + row) * Kdim + k0 + (ch << 3));
        }
    };
    auto store_smem = [&](int buf) {
        const int offAh = (buf * 2 + 0) * 4608;
        const int offAl = (buf * 2 + 1) * 4608;
        const int offBh = 18432 + (buf * 2 + 0) * 9216;
        const int offBl = 18432 + (buf * 2 + 1) * 9216;
#pragma unroll
        for (int p = 0; p < 4; ++p) {
            const int j = tid + (p << 8);
            const int row = j >> 4, c4 = j & 15;
            const float4 v = ra[p];
            __nv_bfloat162 h01 = __float22bfloat162_rn(make_float2(v.x, v.y));
            __nv_bfloat162 h23 = __float22bfloat162_rn(make_float2(v.z, v.w));
            float2 f01 = __bfloat1622float2(h01);
            float2 f23 = __bfloat1622float2(h23);
            __nv_bfloat162 l01 = __float22bfloat162_rn(make_float2(v.x - f01.x, v.y - f01.y));
            __nv_bfloat162 l23 = __float22bfloat162_rn(make_float2(v.z - f23.x, v.w - f23.y));
            const int e = row * 72 + (c4 << 2);
            uint2 hh, ll;
            hh.x = *(uint32_t*)&h01; hh.y = *(uint32_t*)&h23;
            ll.x = *(uint32_t*)&l01; ll.y = *(uint32_t*)&l23;
            *(uint2*)(sm + offAh + e) = hh;
            *(uint2*)(sm + offAl + e) = ll;
        }
#pragma unroll
        for (int p = 0; p < 4; ++p) {
            const int j = tid + (p << 8);
            const int row = j >> 3, ch = j & 7;
            const int e = row * 72 + (ch << 3);
            *(uint4*)(sm + offBh + e) = rbh[p];
            *(uint4*)(sm + offBl + e) = rbl[p];
        }
    };

    load_gmem(0);
    store_smem(0);
    __syncthreads();

    for (int c = 0; c < nch; ++c) {
        const int buf = c & 1;
        if (c + 1 < nch) load_gmem(c + 1);

        const uint32_t aAh = smb + ((buf * 2 + 0) * 4608 + a_re) * 2;
        const uint32_t aAl = smb + ((buf * 2 + 1) * 4608 + a_re) * 2;
        const uint32_t aBh = smb + (18432 + (buf * 2 + 0) * 9216 + b_re) * 2;
        const uint32_t aBl = smb + (18432 + (buf * 2 + 1) * 9216 + b_re) * 2;

#pragma unroll
        for (int ks = 0; ks < 4; ++ks) {
            const uint32_t kb = (uint32_t)(ks << 5);
            uint32_t ah[2][4], al[2][4], bh[2][4], bl[2][4];
#pragma unroll
            for (int mi = 0; mi < 2; ++mi) {
                LDSM4(ah[mi], aAh + kb + mi * (16 * 72 * 2));
                LDSM4(al[mi], aAl + kb + mi * (16 * 72 * 2));
            }
#pragma unroll
            for (int g = 0; g < 2; ++g) {
                LDSM4(bh[g], aBh + kb + g * (16 * 72 * 2));
                LDSM4(bl[g], aBl + kb + g * (16 * 72 * 2));
            }
#pragma unroll
            for (int mi = 0; mi < 2; ++mi)
#pragma unroll
                for (int nj = 0; nj < 4; ++nj) {
                    const uint32_t* ph = &bh[nj >> 1][(nj & 1) << 1];
                    const uint32_t* pl = &bl[nj >> 1][(nj & 1) << 1];
                    MMA_BF16(acc[mi][nj], ah[mi], ph);
                    MMA_BF16(acc[mi][nj], ah[mi], pl);
                    MMA_BF16(acc[mi][nj], al[mi], ph);
                }
        }
        if (c + 1 < nch) {
            store_smem(buf ^ 1);
            __syncthreads();
        }
    }

#pragma unroll
    for (int mi = 0; mi < 2; ++mi) {
        const int row0 = m0 + warp_m * 32 + mi * 16 + (lane >> 2);
#pragma unroll
        for (int nj = 0; nj < 4; ++nj) {
            const int col = n0 + warp_n * 32 + nj * 8 + ((lane & 3) << 1);
            const float b0 = (col     < Nreal) ? bias[col]     : 0.f;
            const float b1 = (col + 1 < Nreal) ? bias[col + 1] : 0.f;
            float o0 = acc[mi][nj][0] + b0, o1 = acc[mi][nj][1] + b1;
            float o2 = acc[mi][nj][2] + b0, o3 = acc[mi][nj][3] + b1;
            if (EPI == 2) {
                const float mk0 = mask[row0], mk1 = mask[row0 + 8];
                o0 = mk0 * fsig(o0);
                o1 = mk0 * fsig(o1);
                o2 = mk1 * fsig(o2);
                o3 = mk1 * fsig(o3);
            }
            if (col < Nreal) {
                C[(size_t)row0 * Nreal + col]       = o0;
                C[(size_t)(row0 + 8) * Nreal + col] = o2;
            }
            if (col + 1 < Nreal) {
                C[(size_t)row0 * Nreal + col + 1]       = o1;
                C[(size_t)(row0 + 8) * Nreal + col + 1] = o3;
            }
        }
    }
}

// ======================= GRU scan (weights in regs, x-preadd) ===============
__global__ void __launch_bounds__(384, 1) gru_scan(
    const float* __restrict__ xW,
    const float* __restrict__ Whh,
    const float* __restrict__ bhh,
    float* __restrict__ out)
{
    __shared__ __align__(16) float hs[128];
    __shared__ float gh[384];

    const int tid = threadIdx.x;
    const int b   = blockIdx.x;

    unsigned long long wv[64];
    {
        const float* wrow = Whh + (size_t)tid * 128;
#pragma unroll
        for (int i = 0; i < 32; ++i) {
            const float4 v = *(const float4*)(wrow + (i << 2));
            wv[2 * i]     = pk2(v.x, v.y);
            wv[2 * i + 1] = pk2(v.z, v.w);
        }
    }
    if (tid < 128) hs[tid] = 0.f;
    const float bh = bhh[tid];

    const float* xrow = xW  + (size_t)b * T_STEPS * 384;
    float*       orow = out + (size_t)b * T_STEPS * 128;

    float xcur = xrow[tid];
    float xn   = (tid < 128) ? xrow[256 + tid] : 0.f;
    __syncthreads();

    const ulonglong2* hp = (const ulonglong2*)hs;

    for (int t = 0; t < T_STEPS; ++t, xrow += 384, orow += 128) {
        unsigned long long acc[8];
#pragma unroll
        for (int q = 0; q < 8; ++q) acc[q] = 0ULL;
#pragma unroll
        for (int i = 0; i < 32; ++i) {
            const ulonglong2 hv = hp[i];
            fma2(acc[(2 * i) & 7],     wv[2 * i],     hv.x);
            fma2(acc[(2 * i + 1) & 7], wv[2 * i + 1], hv.y);
        }
        acc[0] = add2(acc[0], acc[4]);
        acc[1] = add2(acc[1], acc[5]);
        acc[2] = add2(acc[2], acc[6]);
        acc[3] = add2(acc[3], acc[7]);
        acc[0] = add2(acc[0], acc[2]);
        acc[1] = add2(acc[1], acc[3]);
        acc[0] = add2(acc[0], acc[1]);
        const float2 p = upk2(acc[0]);
        const float base = bh + p.x + p.y;
        gh[tid] = (tid < 256) ? base + xcur : base;
        float xc_n = 0.f, xn_n = 0.f;
        if (t + 1 < T_STEPS) {
            xc_n = xrow[384 + tid];
            if (tid < 128) xn_n = xrow[640 + tid];
        }
        __syncthreads();
        if (tid < 128) {
            const float r  = fsig(gh[tid]);
            const float z  = fsig(gh[128 + tid]);
            const float n  = ftanh(xn + r * gh[256 + tid]);
            const float hn = (1.f - z) * n + z * hs[tid];
            hs[tid]   = hn;
            orow[tid] = hn;
        }
        __syncthreads();
        xcur = xc_n;
        xn   = xn_n;
    }
}

// ======================= attention (2 bt / CTA, named barriers) =============
#define ATTN_HALF_FLOATS 8720
#define ATTN_SMEM (2 * ATTN_HALF_FLOATS * 4)

__global__ void __launch_bounds__(256) attn_kernel(
    const float* __restrict__ H, const int* __restrict__ F,
    const float* __restrict__ E, float* __restrict__ S)
{
    extern __shared__ float smf[];
    const int half  = threadIdx.x >> 7;
    const int tid   = threadIdx.x & 127;
    const int lane  = tid & 31;
    const int w     = tid >> 5;
    const int bt    = (blockIdx.x << 1) + half;
    const int barid = 1 + half;          // named barrier per 128-thread half

    float* Es   = smf + half * ATTN_HALF_FLOATS;  // [64][129]
    float* Hsm  = Es + 8256;                      // 128
    float* part = Hsm + 128;                      // 128
    float* wgt  = part + 128;                     // 64
    float* mb   = wgt + 64;                       // 64
    float* red  = mb + 64;                        // 4
    int*   fo   = (int*)(red + 4);                // 64

    if (tid < 64) {
        const int f = F[bt * 64 + tid];
        fo[tid] = f << 7;
        mb[tid] = (f > 0) ? 0.f : -1e30f;
    }
    Hsm[tid] = H[(size_t)bt * 128 + tid];
    BAR_SYNC(barid, 128);

    // stage the 64 gathered E rows into smem
#pragma unroll
    for (int i = 0; i < 16; ++i) {
        const int idx = tid + (i << 7);
        const int r = idx >> 5, c4 = idx & 31;
        const float4 v = *(const float4*)(E + fo[r] + (c4 << 2));
        float* d = Es + r * 129 + (c4 << 2);
        d[0] = v.x; d[1] = v.y; d[2] = v.z; d[3] = v.w;
    }
    BAR_SYNC(barid, 128);

    // half-row dots
    {
        const int a = tid & 63, hf = tid >> 6;
        const float* er = Es + a * 129 + (hf << 6);
        const float* hr = Hsm + (hf << 6);
        float s0 = 0.f, s1 = 0.f, s2 = 0.f, s3 = 0.f;
#pragma unroll
        for (int j = 0; j < 64; j += 4) {
            s0 += er[j]     * hr[j];
            s1 += er[j + 1] * hr[j + 1];
            s2 += er[j + 2] * hr[j + 2];
            s3 += er[j + 3] * hr[j + 3];
        }
        part[tid] = (s0 + s1) + (s2 + s3);
    }
    BAR_SYNC(barid, 128);

    // softmax over 64 (warps 0,1 of this half)
    float e = 0.f, vv = 0.f;
    if (tid < 64) {
        vv = part[tid] + part[tid + 64] + mb[tid];
        float mm = vv;
#pragma unroll
        for (int o = 16; o; o >>= 1) mm = fmaxf(mm, __shfl_xor_sync(0xffffffffu, mm, o));
        if (lane == 0) red[w] = mm;
    }
    BAR_SYNC(barid, 128);
    const float gmax = fmaxf(red[0], red[1]);
    if (tid < 64) {
        e = __expf(vv - gmax);
        float s = e;
#pragma unroll
        for (int o = 16; o; o >>= 1) s += __shfl_xor_sync(0xffffffffu, s, o);
        if (lane == 0) red[2 + w] = s;
    }
    BAR_SYNC(barid, 128);
    if (tid < 64) wgt[tid] = __fdividef(e, red[2] + red[3]);
    BAR_SYNC(barid, 128);

    // weighted sum
    float k0 = 0.f, k1 = 0.f, k2 = 0.f, k3 = 0.f;
#pragma unroll
    for (int a = 0; a < 64; a += 4) {
        k0 += wgt[a]     * Es[a * 129 + tid];
        k1 += wgt[a + 1] * Es[(a + 1) * 129 + tid];
        k2 += wgt[a + 2] * Es[(a + 2) * 129 + tid];
        k3 += wgt[a + 3] * Es[(a + 3) * 129 + tid];
    }
    const float kk = (k0 + k1) + (k2 + k3);

    S[(size_t)bt * 256 + tid]       = Hsm[tid];
    S[(size_t)bt * 256 + 128 + tid] = kk;
}

// ======================= launch ============================================
extern "C" void kernel_launch(void* const* d_in, const int* in_sizes, int n_in,
                              void* d_out, int out_size)
{
    const float* inputs_x = (const float*)d_in[0];
    const int*   inputs_f = (const int*)  d_in[1];
    const float* mask     = (const float*)d_in[2];
    const float* dag_emb  = (const float*)d_in[3];
    const float* embed_a  = (const float*)d_in[4];
    const float* Wih0     = (const float*)d_in[5];
    const float* Whh0     = (const float*)d_in[6];
    const float* bih0     = (const float*)d_in[7];
    const float* bhh0     = (const float*)d_in[8];
    const float* Wih1     = (const float*)d_in[9];
    const float* Whh1     = (const float*)d_in[10];
    const float* bih1     = (const float*)d_in[11];
    const float* bhh1     = (const float*)d_in[12];
    const float* fc_w     = (const float*)d_in[13];
    const float* fc_b     = (const float*)d_in[14];
    float* out = (float*)d_out;

    float *pP, *pxW, *pH, *pS;
    __nv_bfloat16 *pBth, *pBtl, *pW0h, *pW0l, *pW1h, *pW1l, *pWfh, *pWfl;
    cudaGetSymbolAddress((void**)&pP,   g_P);
    cudaGetSymbolAddress((void**)&pxW,  g_xW);
    cudaGetSymbolAddress((void**)&pH,   g_H);
    cudaGetSymbolAddress((void**)&pS,   g_S);
    cudaGetSymbolAddress((void**)&pBth, g_Bth);
    cudaGetSymbolAddress((void**)&pBtl, g_Btl);
    cudaGetSymbolAddress((void**)&pW0h, g_W0h);
    cudaGetSymbolAddress((void**)&pW0l, g_W0l);
    cudaGetSymbolAddress((void**)&pW1h, g_W1h);
    cudaGetSymbolAddress((void**)&pW1l, g_W1l);
    cudaGetSymbolAddress((void**)&pWfh, g_Wfh);
    cudaGetSymbolAddress((void**)&pWfl, g_Wfl);

    cudaFuncSetAttribute(gemm1_mma, cudaFuncAttributeMaxDynamicSharedMemorySize,
                         S1_SMEM);
    cudaFuncSetAttribute(gemm2_fused, cudaFuncAttributeMaxDynamicSharedMemorySize,
                         S1_SMEM);
    cudaFuncSetAttribute(gemmS_mma<1>, cudaFuncAttributeMaxDynamicSharedMemorySize,
                         S1_SMEM);
    cudaFuncSetAttribute(gemmS_mma<2>, cudaFuncAttributeMaxDynamicSharedMemorySize,
                         S1_SMEM);
    cudaFuncSetAttribute(attn_kernel, cudaFuncAttributeMaxDynamicSharedMemorySize,
                         ATTN_SMEM);

    // 0) fused prep
    prep_all<<<1380, 256>>>(dag_emb, Wih0, Wih1, fc_w,
                            pBth, pBtl, pW0h, pW0l, pW1h, pW1l, pWfh, pWfl);
    // 1) split-K x3 partials
    gemm1_mma<<<dim3(100, 3), 256, S1_SMEM>>>(inputs_x, pBth, pBtl, pP);
    // 2) xW0 = tanh(P0+P1+P2) @ Wih0^T + bih0 (fused combine)
    gemm2_fused<<<dim3(100, 3), 256, S1_SMEM>>>(pP, pW0h, pW0l, bih0, pxW);
    // 3) GRU layer 0
    gru_scan<<<128, 384>>>(pxW, Whh0, bhh0, pH);
    // 4) xW1 = H @ Wih1^T + bih1
    gemmS_mma<1><<<dim3(100, 3), 256, S1_SMEM>>>(pH, pW1h, pW1l, bih1, nullptr,
                                                 pxW, 128, 384);
    // 5) GRU layer 1
    gru_scan<<<128, 384>>>(pxW, Whh1, bhh1, pH);
    // 6) attention (2 bt per CTA, named barriers — halves never couple)
    attn_kernel<<<BT_TOTAL / 2, 256, ATTN_SMEM>>>(pH, inputs_f, embed_a, pS);
    // 7) out = sigmoid(S @ fc_w^T + fc_b) * mask
    gemmS_mma<2><<<dim3(100, 3), 256, S1_SMEM>>>(pS, pWfh, pWfl, fc_b, mask,
                                                 out, 256, 283);
}

// round 15
// speedup vs baseline: 1.0144x; 1.0144x over previous
#include <cuda_runtime.h>
#include <cuda_bf16.h>
#include <cstdint>

// ---------------------------------------------------------------------------
// KAME pipeline (champion configuration, round-8):
//   0) prep (ONE launch): splitB_t(dag_emb) + splitW x3 (Wih0/Wih1/fc_w)
//   1) P = inputs_x @ dag_emb partials: gemm1_mma split-K x3
//   2) X = tanh(P0+P1+P2)                       (combine3, fast tanh)
//   3) xW0 = X @ Wih0^T + bih0                  (gemmS_mma<1>)
//   4) H   = GRU-scan(xW0, Whh0, bhh0)          (weights-in-regs, xW prefetch)
//   5) xW1 = H @ Wih1^T + bih1                  (gemmS_mma<1>)
//   6) H   = GRU-scan(xW1, Whh1, bhh1)
//   7) S   = [H, attention(H, embed_a[inputs_f])]  (1 bt / 128-thr CTA)
//   8) out = sigmoid(S @ fc_w^T + fc_b) * mask     (gemmS_mma<2>)
// ---------------------------------------------------------------------------

#define BT_TOTAL 6400
#define T_STEPS  50
#define K1       4880
#define N1       128

__device__ float g_X [BT_TOTAL * 128];
__device__ float g_P [3 * BT_TOTAL * 128];   // split-K partials
__device__ float g_xW[BT_TOTAL * 384];
__device__ float g_H [BT_TOTAL * 128];
__device__ float g_S [BT_TOTAL * 256];
__device__ __nv_bfloat16 g_Bth[N1 * K1];
__device__ __nv_bfloat16 g_Btl[N1 * K1];
__device__ __nv_bfloat16 g_W0h[384 * 128], g_W0l[384 * 128];
__device__ __nv_bfloat16 g_W1h[384 * 128], g_W1l[384 * 128];
__device__ __nv_bfloat16 g_Wfh[384 * 256], g_Wfl[384 * 256];

// ======================= PTX helpers =======================================
__device__ __forceinline__ uint32_t smem_u32(const void* p) {
    uint32_t a;
    asm("{ .reg .u64 t; cvta.to.shared.u64 t, %1; cvt.u32.u64 %0, t; }" : "=r"(a) : "l"(p));
    return a;
}
#define LDSM4(r, addr) \
    asm volatile("ldmatrix.sync.aligned.m8n8.x4.shared.b16 {%0,%1,%2,%3}, [%4];" \
        : "=r"((r)[0]), "=r"((r)[1]), "=r"((r)[2]), "=r"((r)[3]) : "r"(addr))
#define MMA_BF16(d, a, b) \
    asm volatile("mma.sync.aligned.m16n8k16.row.col.f32.bf16.bf16.f32 " \
        "{%0,%1,%2,%3}, {%4,%5,%6,%7}, {%8,%9}, {%0,%1,%2,%3};" \
        : "+f"((d)[0]), "+f"((d)[1]), "+f"((d)[2]), "+f"((d)[3]) \
        : "r"((a)[0]), "r"((a)[1]), "r"((a)[2]), "r"((a)[3]), \
          "r"((b)[0]), "r"((b)[1]))

__device__ __forceinline__ unsigned long long pk2(float x, float y) {
    unsigned long long r;
    asm("mov.b64 %0, {%1, %2};" : "=l"(r) : "f"(x), "f"(y));
    return r;
}
__device__ __forceinline__ void fma2(unsigned long long& d,
                                     unsigned long long a, unsigned long long b) {
    asm("fma.rn.f32x2 %0, %1, %2, %0;" : "+l"(d) : "l"(a), "l"(b));
}
__device__ __forceinline__ unsigned long long add2(unsigned long long a,
                                                   unsigned long long b) {
    unsigned long long r;
    asm("add.rn.f32x2 %0, %1, %2;" : "=l"(r) : "l"(a), "l"(b));
    return r;
}
__device__ __forceinline__ float2 upk2(unsigned long long v) {
    float lo, hi;
    asm("mov.b64 {%0, %1}, %2;" : "=f"(lo), "=f"(hi) : "l"(v));
    return make_float2(lo, hi);
}

// ---- fast transcendental helpers (MUFU-based, rel err ~1e-6) --------------
__device__ __forceinline__ float fsig(float x) {
    return __fdividef(1.f, 1.f + __expf(-x));
}
__device__ __forceinline__ float ftanh(float x) {
    return 1.f - __fdividef(2.f, 1.f + __expf(2.f * x));
}

// ======================= stage 0: fused prep (1 launch) ====================
__global__ void __launch_bounds__(256) prep_all(
    const float* __restrict__ dag,
    const float* __restrict__ W0, const float* __restrict__ W1,
    const float* __restrict__ Wf,
    __nv_bfloat16* __restrict__ Bh,  __nv_bfloat16* __restrict__ Bl,
    __nv_bfloat16* __restrict__ W0h, __nv_bfloat16* __restrict__ W0l,
    __nv_bfloat16* __restrict__ W1h, __nv_bfloat16* __restrict__ W1l,
    __nv_bfloat16* __restrict__ Wfh, __nv_bfloat16* __restrict__ Wfl)
{
    __shared__ float t[32][33];
    const int b = blockIdx.x;
    if (b < 612) {
        const int k0 = (b % 153) << 5;
        const int n0 = (b / 153) << 5;
        const int tx = threadIdx.x & 31, ty = threadIdx.x >> 5;
#pragma unroll
        for (int r = ty; r < 32; r += 8) {
            const int k = k0 + r;
            t[r][tx] = (k < K1) ? dag[(size_t)k * N1 + n0 + tx] : 0.f;
        }
        __syncthreads();
#pragma unroll
        for (int r = ty; r < 32; r += 8) {
            const int n = n0 + r, k = k0 + tx;
            if (k < K1) {
                const float v = t[tx][r];
                const __nv_bfloat16 h = __float2bfloat16(v);
                Bh[(size_t)n * K1 + k] = h;
                Bl[(size_t)n * K1 + k] = __float2bfloat16(v - __bfloat162float(h));
            }
        }
    } else {
        const float* W; __nv_bfloat16 *Wh, *Wl; int base, total, valid;
        if (b < 804)      { W = W0; Wh = W0h; Wl = W0l; base = 612; total = 49152;  valid = 49152; }
        else if (b < 996) { W = W1; Wh = W1h; Wl = W1l; base = 804; total = 49152;  valid = 49152; }
        else              { W = Wf; Wh = Wfh; Wl = Wfl; base = 996; total = 98304;  valid = 72448; }
        const int idx = (b - base) * 256 + threadIdx.x;
        if (idx < total) {
            const float v = (idx < valid) ? W[idx] : 0.f;
            const __nv_bfloat16 h = __float2bfloat16(v);
            Wh[idx] = h;
            Wl[idx] = __float2bfloat16(v - __bfloat162float(h));
        }
    }
}

// ======================= stage 1: mma.sync split GEMM (split-K x3) =========
#define S1_NCH 77
#define S1_KSPLIT 26
#define S1_SMEM (55296 * 2)

__global__ void __launch_bounds__(256) gemm1_mma(
    const float* __restrict__ A,
    const __nv_bfloat16* __restrict__ Bth,
    const __nv_bfloat16* __restrict__ Btl,
    float* __restrict__ P)
{
    extern __shared__ __align__(16) __nv_bfloat16 sm[];
    const uint32_t smb = smem_u32(sm);

    const int tid    = threadIdx.x;
    const int lane   = tid & 31;
    const int wid    = tid >> 5;
    const int warp_m = wid & 1;
    const int warp_n = wid >> 1;
    const int m0     = blockIdx.x << 6;
    const int zz     = blockIdx.y;
    const int c0     = zz * S1_KSPLIT;
    const int c1     = (c0 + S1_KSPLIT < S1_NCH) ? c0 + S1_KSPLIT : S1_NCH;
    float* const Cp  = P + (size_t)zz * BT_TOTAL * 128;

    const int a_re = (warp_m * 32 + (lane & 15)) * 72 + ((lane >> 4) << 3);
    const int b_re = (warp_n * 32 + (lane & 7) + ((lane >> 4) & 1) * 8) * 72
                   + (((lane >> 3) & 1) << 3);

    float acc[2][4][4];
#pragma unroll
    for (int i = 0; i < 2; ++i)
#pragma unroll
        for (int j = 0; j < 4; ++j)
#pragma unroll
            for (int q = 0; q < 4; ++q) acc[i][j][q] = 0.f;

    float4 ra[4];
    uint4  rbh[4], rbl[4];

    auto load_gmem = [&](int c) {
        const int k0 = c << 6;
        if (c < 76) {
#pragma unroll
            for (int p = 0; p < 4; ++p) {
                const int j = tid + (p << 8);
                const int row = j >> 4, c4 = j & 15;
                ra[p] = *(const float4*)(A + (size_t)(m0 + row) * K1 + k0 + (c4 << 2));
            }
#pragma unroll
            for (int p = 0; p < 4; ++p) {
                const int j = tid + (p << 8);
                const int row = j >> 3, ch = j & 7;
                rbh[p] = *(const uint4*)(Bth + (size_t)row * K1 + k0 + (ch << 3));
                rbl[p] = *(const uint4*)(Btl + (size_t)row * K1 + k0 + (ch << 3));
            }
        } else {
            {
                const int row = tid >> 2, c4 = tid & 3;
                ra[0] = *(const float4*)(A + (size_t)(m0 + row) * K1 + k0 + (c4 << 2));
            }
            {
                const int row = tid >> 1, ch = tid & 1;
                rbh[0] = *(const uint4*)(Bth + (size_t)row * K1 + k0 + (ch << 3));
                rbl[0] = *(const uint4*)(Btl + (size_t)row * K1 + k0 + (ch << 3));
            }
        }
    };
    auto store_smem = [&](int c, int buf) {
        const int offAh = (buf * 2 + 0) * 4608;
        const int offAl = (buf * 2 + 1) * 4608;
        const int offBh = 18432 + (buf * 2 + 0) * 9216;
        const int offBl = 18432 + (buf * 2 + 1) * 9216;
        if (c < 76) {
#pragma unroll
            for (int p = 0; p < 4; ++p) {
                const int j = tid + (p << 8);
                const int row = j >> 4, c4 = j & 15;
                const float4 v = ra[p];
                __nv_bfloat162 h01 = __float22bfloat162_rn(make_float2(v.x, v.y));
                __nv_bfloat162 h23 = __float22bfloat162_rn(make_float2(v.z, v.w));
                float2 f01 = __bfloat1622float2(h01);
                float2 f23 = __bfloat1622float2(h23);
                __nv_bfloat162 l01 = __float22bfloat162_rn(make_float2(v.x - f01.x, v.y - f01.y));
                __nv_bfloat162 l23 = __float22bfloat162_rn(make_float2(v.z - f23.x, v.w - f23.y));
                const int e = row * 72 + (c4 << 2);
                uint2 hh, ll;
                hh.x = *(uint32_t*)&h01; hh.y = *(uint32_t*)&h23;
                ll.x = *(uint32_t*)&l01; ll.y = *(uint32_t*)&l23;
                *(uint2*)(sm + offAh + e) = hh;
                *(uint2*)(sm + offAl + e) = ll;
            }
#pragma unroll
            for (int p = 0; p < 4; ++p) {
                const int j = tid + (p << 8);
                const int row = j >> 3, ch = j & 7;
                const int e = row * 72 + (ch << 3);
                *(uint4*)(sm + offBh + e) = rbh[p];
                *(uint4*)(sm + offBl + e) = rbl[p];
            }
        } else {
            {
                const int row = tid >> 2, c4 = tid & 3;
                const float4 v = ra[0];
                __nv_bfloat162 h01 = __float22bfloat162_rn(make_float2(v.x, v.y));
                __nv_bfloat162 h23 = __float22bfloat162_rn(make_float2(v.z, v.w));
                float2 f01 = __bfloat1622float2(h01);
                float2 f23 = __bfloat1622float2(h23);
                __nv_bfloat162 l01 = __float22bfloat162_rn(make_float2(v.x - f01.x, v.y - f01.y));
                __nv_bfloat162 l23 = __float22bfloat162_rn(make_float2(v.z - f23.x, v.w - f23.y));
                const int e = row * 72 + (c4 << 2);
                uint2 hh, ll;
                hh.x = *(uint32_t*)&h01; hh.y = *(uint32_t*)&h23;
                ll.x = *(uint32_t*)&l01; ll.y = *(uint32_t*)&l23;
                *(uint2*)(sm + offAh + e) = hh;
                *(uint2*)(sm + offAl + e) = ll;
            }
            {
                const int row = tid >> 1, ch = tid & 1;
                const int e = row * 72 + (ch << 3);
                *(uint4*)(sm + offBh + e) = rbh[0];
                *(uint4*)(sm + offBl + e) = rbl[0];
            }
        }
    };

    load_gmem(c0);
    store_smem(c0, 0);
    __syncthreads();

    for (int c = c0; c < c1; ++c) {
        const int buf = (c - c0) & 1;
        if (c + 1 < c1) load_gmem(c + 1);

        const uint32_t aAh = smb + ((buf * 2 + 0) * 4608 + a_re) * 2;
        const uint32_t aAl = smb + ((buf * 2 + 1) * 4608 + a_re) * 2;
        const uint32_t aBh = smb + (18432 + (buf * 2 + 0) * 9216 + b_re) * 2;
        const uint32_t aBl = smb + (18432 + (buf * 2 + 1) * 9216 + b_re) * 2;

        const int ksteps = (c < 76) ? 4 : 1;
        for (int ks = 0; ks < ksteps; ++ks) {
            const uint32_t kb = (uint32_t)(ks << 5);
            uint32_t ah[2][4], al[2][4], bh[2][4], bl[2][4];
#pragma unroll
            for (int mi = 0; mi < 2; ++mi) {
                LDSM4(ah[mi], aAh + kb + mi * (16 * 72 * 2));
                LDSM4(al[mi], aAl + kb + mi * (16 * 72 * 2));
            }
#pragma unroll
            for (int g = 0; g < 2; ++g) {
                LDSM4(bh[g], aBh + kb + g * (16 * 72 * 2));
                LDSM4(bl[g], aBl + kb + g * (16 * 72 * 2));
            }
#pragma unroll
            for (int mi = 0; mi < 2; ++mi)
#pragma unroll
                for (int nj = 0; nj < 4; ++nj) {
                    const uint32_t* ph = &bh[nj >> 1][(nj & 1) << 1];
                    const uint32_t* pl = &bl[nj >> 1][(nj & 1) << 1];
                    MMA_BF16(acc[mi][nj], ah[mi], ph);
                    MMA_BF16(acc[mi][nj], ah[mi], pl);
                    MMA_BF16(acc[mi][nj], al[mi], ph);
                }
        }
        if (c + 1 < c1) {
            store_smem(c + 1, buf ^ 1);
            __syncthreads();
        }
    }

#pragma unroll
    for (int mi = 0; mi < 2; ++mi) {
        const int row0 = m0 + warp_m * 32 + mi * 16 + (lane >> 2);
#pragma unroll
        for (int nj = 0; nj < 4; ++nj) {
            const int col = warp_n * 32 + nj * 8 + ((lane & 3) << 1);
            *(float2*)(Cp + (size_t)row0 * 128 + col) =
                make_float2(acc[mi][nj][0], acc[mi][nj][1]);
            *(float2*)(Cp + (size_t)(row0 + 8) * 128 + col) =
                make_float2(acc[mi][nj][2], acc[mi][nj][3]);
        }
    }
}

// combine split-K partials + fast tanh
__global__ void __launch_bounds__(256) combine3(
    const float* __restrict__ P, float* __restrict__ X)
{
    const int i = blockIdx.x * 256 + threadIdx.x;
    const float4 a = ((const float4*)P)[i];
    const float4 b = ((const float4*)(P + (size_t)BT_TOTAL * 128))[i];
    const float4 c = ((const float4*)(P + (size_t)2 * BT_TOTAL * 128))[i];
    float4 o;
    o.x = ftanh(a.x + b.x + c.x);
    o.y = ftanh(a.y + b.y + c.y);
    o.z = ftanh(a.z + b.z + c.z);
    o.w = ftanh(a.w + b.w + c.w);
    ((float4*)X)[i] = o;
}

// ======================= small mma GEMM (stages 3,5,8) =====================
template<int EPI>  // 1 = +bias; 2 = mask*sigmoid(+bias)
__global__ void __launch_bounds__(256) gemmS_mma(
    const float* __restrict__ A,
    const __nv_bfloat16* __restrict__ Bh,
    const __nv_bfloat16* __restrict__ Bl,
    const float* __restrict__ bias,
    const float* __restrict__ mask,
    float* __restrict__ C, int Kdim, int Nreal)
{
    extern __shared__ __align__(16) __nv_bfloat16 sm[];
    const uint32_t smb = smem_u32(sm);

    const int tid    = threadIdx.x;
    const int lane   = tid & 31;
    const int wid    = tid >> 5;
    const int warp_m = wid & 1;
    const int warp_n = wid >> 1;
    const int m0     = blockIdx.x << 6;
    const int n0     = blockIdx.y << 7;
    const int nch    = Kdim >> 6;

    const int a_re = (warp_m * 32 + (lane & 15)) * 72 + ((lane >> 4) << 3);
    const int b_re = (warp_n * 32 + (lane & 7) + ((lane >> 4) & 1) * 8) * 72
                   + (((lane >> 3) & 1) << 3);

    float acc[2][4][4];
#pragma unroll
    for (int i = 0; i < 2; ++i)
#pragma unroll
        for (int j = 0; j < 4; ++j)
#pragma unroll
            for (int q = 0; q < 4; ++q) acc[i][j][q] = 0.f;

    float4 ra[4];
    uint4  rbh[4], rbl[4];

    auto load_gmem = [&](int c) {
        const int k0 = c << 6;
#pragma unroll
        for (int p = 0; p < 4; ++p) {
            const int j = tid + (p << 8);
            const int row = j >> 4, c4 = j & 15;
            ra[p] = *(const float4*)(A + (size_t)(m0 + row) * Kdim + k0 + (c4 << 2));
        }
#pragma unroll
        for (int p = 0; p < 4; ++p) {
            const int j = tid + (p << 8);
            const int row = j >> 3, ch = j & 7;
            rbh[p] = *(const uint4*)(Bh + (size_t)(n0 + row) * Kdim + k0 + (ch << 3));
            rbl[p] = *(const uint4*)(Bl + (size_t)(n0 + row) * Kdim + k0 + (ch << 3));
        }
    };
    auto store_smem = [&](int buf) {
        const int offAh = (buf * 2 + 0) * 4608;
        const int offAl = (buf * 2 + 1) * 4608;
        const int offBh = 18432 + (buf * 2 + 0) * 9216;
        const int offBl = 18432 + (buf * 2 + 1) * 9216;
#pragma unroll
        for (int p = 0; p < 4; ++p) {
            const int j = tid + (p << 8);
            const int row = j >> 4, c4 = j & 15;
            const float4 v = ra[p];
            __nv_bfloat162 h01 = __float22bfloat162_rn(make_float2(v.x, v.y));
            __nv_bfloat162 h23 = __float22bfloat162_rn(make_float2(v.z, v.w));
            float2 f01 = __bfloat1622float2(h01);
            float2 f23 = __bfloat1622float2(h23);
            __nv_bfloat162 l01 = __float22bfloat162_rn(make_float2(v.x - f01.x, v.y - f01.y));
            __nv_bfloat162 l23 = __float22bfloat162_rn(make_float2(v.z - f23.x, v.w - f23.y));
            const int e = row * 72 + (c4 << 2);
            uint2 hh, ll;
            hh.x = *(uint32_t*)&h01; hh.y = *(uint32_t*)&h23;
            ll.x = *(uint32_t*)&l01; ll.y = *(uint32_t*)&l23;
            *(uint2*)(sm + offAh + e) = hh;
            *(uint2*)(sm + offAl + e) = ll;
        }
#pragma unroll
        for (int p = 0; p < 4; ++p) {
            const int j = tid + (p << 8);
            const int row = j >> 3, ch = j & 7;
            const int e = row * 72 + (ch << 3);
            *(uint4*)(sm + offBh + e) = rbh[p];
            *(uint4*)(sm + offBl + e) = rbl[p];
        }
    };

    load_gmem(0);
    store_smem(0);
    __syncthreads();

    for (int c = 0; c < nch; ++c) {
        const int buf = c & 1;
        if (c + 1 < nch) load_gmem(c + 1);

        const uint32_t aAh = smb + ((buf * 2 + 0) * 4608 + a_re) * 2;
        const uint32_t aAl = smb + ((buf * 2 + 1) * 4608 + a_re) * 2;
        const uint32_t aBh = smb + (18432 + (buf * 2 + 0) * 9216 + b_re) * 2;
        const uint32_t aBl = smb + (18432 + (buf * 2 + 1) * 9216 + b_re) * 2;

#pragma unroll
        for (int ks = 0; ks < 4; ++ks) {
            const uint32_t kb = (uint32_t)(ks << 5);
            uint32_t ah[2][4], al[2][4], bh[2][4], bl[2][4];
#pragma unroll
            for (int mi = 0; mi < 2; ++mi) {
                LDSM4(ah[mi], aAh + kb + mi * (16 * 72 * 2));
                LDSM4(al[mi], aAl + kb + mi * (16 * 72 * 2));
            }
#pragma unroll
            for (int g = 0; g < 2; ++g) {
                LDSM4(bh[g], aBh + kb + g * (16 * 72 * 2));
                LDSM4(bl[g], aBl + kb + g * (16 * 72 * 2));
            }
#pragma unroll
            for (int mi = 0; mi < 2; ++mi)
#pragma unroll
                for (int nj = 0; nj < 4; ++nj) {
                    const uint32_t* ph = &bh[nj >> 1][(nj & 1) << 1];
                    const uint32_t* pl = &bl[nj >> 1][(nj & 1) << 1];
                    MMA_BF16(acc[mi][nj], ah[mi], ph);
                    MMA_BF16(acc[mi][nj], ah[mi], pl);
                    MMA_BF16(acc[mi][nj], al[mi], ph);
                }
        }
        if (c + 1 < nch) {
            store_smem(buf ^ 1);
            __syncthreads();
        }
    }

#pragma unroll
    for (int mi = 0; mi < 2; ++mi) {
        const int row0 = m0 + warp_m * 32 + mi * 16 + (lane >> 2);
#pragma unroll
        for (int nj = 0; nj < 4; ++nj) {
            const int col = n0 + warp_n * 32 + nj * 8 + ((lane & 3) << 1);
            const float b0 = (col     < Nreal) ? bias[col]     : 0.f;
            const float b1 = (col + 1 < Nreal) ? bias[col + 1] : 0.f;
            float o0 = acc[mi][nj][0] + b0, o1 = acc[mi][nj][1] + b1;
            float o2 = acc[mi][nj][2] + b0, o3 = acc[mi][nj][3] + b1;
            if (EPI == 2) {
                const float mk0 = mask[row0], mk1 = mask[row0 + 8];
                o0 = mk0 * fsig(o0);
                o1 = mk0 * fsig(o1);
                o2 = mk1 * fsig(o2);
                o3 = mk1 * fsig(o3);
            }
            if (col < Nreal) {
                C[(size_t)row0 * Nreal + col]       = o0;
                C[(size_t)(row0 + 8) * Nreal + col] = o2;
            }
            if (col + 1 < Nreal) {
                C[(size_t)row0 * Nreal + col + 1]       = o1;
                C[(size_t)(row0 + 8) * Nreal + col + 1] = o3;
            }
        }
    }
}

// ======================= GRU scan (weights in regs, xW prefetch) ============
__global__ void __launch_bounds__(384, 1) gru_scan(
    const float* __restrict__ xW,
    const float* __restrict__ Whh,
    const float* __restrict__ bhh,
    float* __restrict__ out)
{
    __shared__ __align__(16) float hs[128];
    __shared__ float gh[384];

    const int tid = threadIdx.x;
    const int b   = blockIdx.x;

    unsigned long long wv[64];
    {
        const float* wrow = Whh + (size_t)tid * 128;
#pragma unroll
        for (int i = 0; i < 32; ++i) {
            const float4 v = *(const float4*)(wrow + (i << 2));
            wv[2 * i]     = pk2(v.x, v.y);
            wv[2 * i + 1] = pk2(v.z, v.w);
        }
    }
    if (tid < 128) hs[tid] = 0.f;
    const float bh = bhh[tid];

    const float* xrow = xW  + (size_t)b * T_STEPS * 384;
    float*       orow = out + (size_t)b * T_STEPS * 128;

    float xr = 0.f, xz = 0.f, xn = 0.f;
    if (tid < 128) {
        xr = xrow[tid]; xz = xrow[128 + tid]; xn = xrow[256 + tid];
    }
    __syncthreads();

    const ulonglong2* hp = (const ulonglong2*)hs;

    for (int t = 0; t < T_STEPS; ++t, xrow += 384, orow += 128) {
        unsigned long long acc[8];
#pragma unroll
        for (int q = 0; q < 8; ++q) acc[q] = 0ULL;
#pragma unroll
        for (int i = 0; i < 32; ++i) {
            const ulonglong2 hv = hp[i];
            fma2(acc[(2 * i) & 7],     wv[2 * i],     hv.x);
            fma2(acc[(2 * i + 1) & 7], wv[2 * i + 1], hv.y);
        }
        acc[0] = add2(acc[0], acc[4]);
        acc[1] = add2(acc[1], acc[5]);
        acc[2] = add2(acc[2], acc[6]);
        acc[3] = add2(acc[3], acc[7]);
        acc[0] = add2(acc[0], acc[2]);
        acc[1] = add2(acc[1], acc[3]);
        acc[0] = add2(acc[0], acc[1]);
        const float2 p = upk2(acc[0]);
        gh[tid] = bh + p.x + p.y;
        __syncthreads();
        if (tid < 128) {
            const float r  = fsig(xr + gh[tid]);
            const float z  = fsig(xz + gh[128 + tid]);
            const float n  = ftanh(xn + r * gh[256 + tid]);
            const float hn = (1.f - z) * n + z * hs[tid];
            hs[tid]   = hn;
            orow[tid] = hn;
            if (t + 1 < T_STEPS) {
                xr = xrow[384 + tid];
                xz = xrow[384 + 128 + tid];
                xn = xrow[384 + 256 + tid];
            }
        }
        __syncthreads();
    }
}

// ======================= attention (1 bt / 128-thr CTA) =====================
__global__ void __launch_bounds__(128) attn_kernel(
    const float* __restrict__ H, const int* __restrict__ F,
    const float* __restrict__ E, float* __restrict__ S)
{
    __shared__ float Es[64][129];
    __shared__ float Hsm[128];
    __shared__ int   fo[64];
    __shared__ float mb[64];
    __shared__ float part[128];
    __shared__ float wgt[64];
    __shared__ float red[4];

    const int bt   = blockIdx.x;
    const int tid  = threadIdx.x;
    const int lane = tid & 31;
    const int w    = tid >> 5;

    if (tid < 64) {
        const int f = F[bt * 64 + tid];
        fo[tid] = f << 7;
        mb[tid] = (f > 0) ? 0.f : -1e30f;
    }
    Hsm[tid] = H[(size_t)bt * 128 + tid];
    __syncthreads();

#pragma unroll
    for (int i = 0; i < 16; ++i) {
        const int idx = tid + (i << 7);
        const int r = idx >> 5, c4 = idx & 31;
        const float4 v = *(const float4*)(E + fo[r] + (c4 << 2));
        float* d = &Es[r][c4 << 2];
        d[0] = v.x; d[1] = v.y; d[2] = v.z; d[3] = v.w;
    }
    __syncthreads();

    {
        const int a = tid & 63, hf = tid >> 6;
        const float* er = &Es[a][hf << 6];
        const float* hr = &Hsm[hf << 6];
        float s0 = 0.f, s1 = 0.f, s2 = 0.f, s3 = 0.f;
#pragma unroll
        for (int j = 0; j < 64; j += 4) {
            s0 += er[j]     * hr[j];
            s1 += er[j + 1] * hr[j + 1];
            s2 += er[j + 2] * hr[j + 2];
            s3 += er[j + 3] * hr[j + 3];
        }
        part[tid] = (s0 + s1) + (s2 + s3);
    }
    __syncthreads();

    float e = 0.f, vv = 0.f;
    if (tid < 64) {
        vv = part[tid] + part[tid + 64] + mb[tid];
        float mm = vv;
#pragma unroll
        for (int o = 16; o; o >>= 1) mm = fmaxf(mm, __shfl_xor_sync(0xffffffffu, mm, o));
        if (lane == 0) red[w] = mm;
    }
    __syncthreads();
    const float gmax = fmaxf(red[0], red[1]);
    if (tid < 64) {
        e = __expf(vv - gmax);
        float s = e;
#pragma unroll
        for (int o = 16; o; o >>= 1) s += __shfl_xor_sync(0xffffffffu, s, o);
        if (lane == 0) red[2 + w] = s;
    }
    __syncthreads();
    if (tid < 64) wgt[tid] = __fdividef(e, red[2] + red[3]);
    __syncthreads();

    float k0 = 0.f, k1 = 0.f, k2 = 0.f, k3 = 0.f;
#pragma unroll
    for (int a = 0; a < 64; a += 4) {
        k0 += wgt[a]     * Es[a][tid];
        k1 += wgt[a + 1] * Es[a + 1][tid];
        k2 += wgt[a + 2] * Es[a + 2][tid];
        k3 += wgt[a + 3] * Es[a + 3][tid];
    }
    const float kk = (k0 + k1) + (k2 + k3);

    S[(size_t)bt * 256 + tid]       = Hsm[tid];
    S[(size_t)bt * 256 + 128 + tid] = kk;
}

// ======================= launch ============================================
extern "C" void kernel_launch(void* const* d_in, const int* in_sizes, int n_in,
                              void* d_out, int out_size)
{
    const float* inputs_x = (const float*)d_in[0];
    const int*   inputs_f = (const int*)  d_in[1];
    const float* mask     = (const float*)d_in[2];
    const float* dag_emb  = (const float*)d_in[3];
    const float* embed_a  = (const float*)d_in[4];
    const float* Wih0     = (const float*)d_in[5];
    const float* Whh0     = (const float*)d_in[6];
    const float* bih0     = (const float*)d_in[7];
    const float* bhh0     = (const float*)d_in[8];
    const float* Wih1     = (const float*)d_in[9];
    const float* Whh1     = (const float*)d_in[10];
    const float* bih1     = (const float*)d_in[11];
    const float* bhh1     = (const float*)d_in[12];
    const float* fc_w     = (const float*)d_in[13];
    const float* fc_b     = (const float*)d_in[14];
    float* out = (float*)d_out;

    float *pX, *pP, *pxW, *pH, *pS;
    __nv_bfloat16 *pBth, *pBtl, *pW0h, *pW0l, *pW1h, *pW1l, *pWfh, *pWfl;
    cudaGetSymbolAddress((void**)&pX,   g_X);
    cudaGetSymbolAddress((void**)&pP,   g_P);
    cudaGetSymbolAddress((void**)&pxW,  g_xW);
    cudaGetSymbolAddress((void**)&pH,   g_H);
    cudaGetSymbolAddress((void**)&pS,   g_S);
    cudaGetSymbolAddress((void**)&pBth, g_Bth);
    cudaGetSymbolAddress((void**)&pBtl, g_Btl);
    cudaGetSymbolAddress((void**)&pW0h, g_W0h);
    cudaGetSymbolAddress((void**)&pW0l, g_W0l);
    cudaGetSymbolAddress((void**)&pW1h, g_W1h);
    cudaGetSymbolAddress((void**)&pW1l, g_W1l);
    cudaGetSymbolAddress((void**)&pWfh, g_Wfh);
    cudaGetSymbolAddress((void**)&pWfl, g_Wfl);

    cudaFuncSetAttribute(gemm1_mma, cudaFuncAttributeMaxDynamicSharedMemorySize,
                         S1_SMEM);
    cudaFuncSetAttribute(gemmS_mma<1>, cudaFuncAttributeMaxDynamicSharedMemorySize,
                         S1_SMEM);
    cudaFuncSetAttribute(gemmS_mma<2>, cudaFuncAttributeMaxDynamicSharedMemorySize,
                         S1_SMEM);

    // 0) fused prep (splitB + 3x splitW in ONE launch)
    prep_all<<<1380, 256>>>(dag_emb, Wih0, Wih1, fc_w,
                            pBth, pBtl, pW0h, pW0l, pW1h, pW1l, pWfh, pWfl);
    // 1) X = tanh(inputs_x @ dag_emb): split-K x3 + combine
    gemm1_mma<<<dim3(100, 3), 256, S1_SMEM>>>(inputs_x, pBth, pBtl, pP);
    combine3<<<BT_TOTAL * 128 / 4 / 256, 256>>>(pP, pX);
    // 2) xW0 = X @ Wih0^T + bih0
    gemmS_mma<1><<<dim3(100, 3), 256, S1_SMEM>>>(pX, pW0h, pW0l, bih0, nullptr,
                                                 pxW, 128, 384);
    // 3) GRU layer 0
    gru_scan<<<128, 384>>>(pxW, Whh0, bhh0, pH);
    // 4) xW1 = H @ Wih1^T + bih1
    gemmS_mma<1><<<dim3(100, 3), 256, S1_SMEM>>>(pH, pW1h, pW1l, bih1, nullptr,
                                                 pxW, 128, 384);
    // 5) GRU layer 1
    gru_scan<<<128, 384>>>(pxW, Whh1, bhh1, pH);
    // 6) attention
    attn_kernel<<<BT_TOTAL, 128>>>(pH, inputs_f, embed_a, pS);
    // 7) out = sigmoid(S @ fc_w^T + fc_b) * mask
    gemmS_mma<2><<<dim3(100, 3), 256, S1_SMEM>>>(pS, pWfh, pWfl, fc_b, mask,
                                                 out, 256, 283);
}